// round 8
// baseline (speedup 1.0000x reference)
#include <cuda_runtime.h>
#include <cuda_fp16.h>
#include <cstdint>

#define D 64
#define KTOT 2048
#define MTILE 128
#define NCHUNK 128
#define NCHUNKS (KTOT / NCHUNK)   // 16
#define TPB 256
#define GRID_P 296                // 148 SMs x 2 CTAs resident
#define NTILES_TOT 512            // 65536 / MTILE

#define SA 68             // A smem row stride (f32)
#define SBROW 132         // B smem row stride in uint2 (1056 B)

#define OFF_A  0
#define A_BYTES (MTILE * SA * 4)                  // 34816
#define OFF_B0 A_BYTES
#define B_BYTES (32 * SBROW * 8)                  // 33792 (32 k-pair rows)
#define OFF_B1 (OFF_B0 + B_BYTES)                 // 68608
#define OFF_HN (OFF_B1 + B_BYTES)                 // 102400
#define OFF_BK (OFF_HN + KTOT * 4)                // 110592
#define SMEM_TOTAL (OFF_BK + MTILE * 4)           // 111104

// ---------------- device scratch (no runtime allocation) ----------------
__device__ float g_halfnorm[KTOT];
// [chunk][kpair(32)][n(128)] -> (h0|h1<<16, l0|l1<<16)
__device__ __align__(16) uint2 g_bsplit[NCHUNKS * 32 * NCHUNK];

// ---------------- helpers ----------------
__device__ __forceinline__ uint32_t smem_u32(const void* p) {
    uint32_t a;
    asm("{ .reg .u64 t; cvta.to.shared.u64 t, %1; cvt.u32.u64 %0, t; }" : "=r"(a) : "l"(p));
    return a;
}
__device__ __forceinline__ void split_f16(float x, uint16_t& h, uint16_t& l) {
    __half hh = __float2half_rn(x);
    __half ll = __float2half_rn(x - __half2float(hh));
    h = __half_as_ushort(hh);
    l = __half_as_ushort(ll);
}
__device__ __forceinline__ void mma_f16(float& c0, float& c1, float& c2, float& c3,
                                        uint32_t a0, uint32_t a1, uint32_t a2, uint32_t a3,
                                        uint32_t b0, uint32_t b1) {
    asm volatile(
        "mma.sync.aligned.m16n8k16.row.col.f32.f16.f16.f32 "
        "{%0,%1,%2,%3}, {%4,%5,%6,%7}, {%8,%9}, {%0,%1,%2,%3};"
        : "+f"(c0), "+f"(c1), "+f"(c2), "+f"(c3)
        : "r"(a0), "r"(a1), "r"(a2), "r"(a3), "r"(b0), "r"(b1));
}
#define CP_ASYNC16(dst, src) \
    asm volatile("cp.async.cg.shared.global [%0], [%1], 16;" :: "r"(dst), "l"(src) : "memory")
#define CP_COMMIT() asm volatile("cp.async.commit_group;" ::: "memory")
#define CP_WAIT1()  asm volatile("cp.async.wait_group 1;" ::: "memory")

// ---------------- fused prep kernel (halfnorm + fp16 h/l split) ----------------
__global__ void prep_kernel(const float* __restrict__ c) {
    int kc = blockIdx.x * blockDim.x + threadIdx.x;   // one centroid per thread
    if (kc >= KTOT) return;
    const int chunk = kc >> 7, n = kc & 127;
    uint2* dst = g_bsplit + chunk * (32 * NCHUNK) + n;
    float s = 0.f;
#pragma unroll
    for (int i = 0; i < D / 4; i++) {
        float4 v = ((const float4*)(c + (size_t)kc * D))[i];
        s += v.x * v.x + v.y * v.y + v.z * v.z + v.w * v.w;
        uint16_t h0, l0, h1, l1, h2, l2, h3, l3;
        split_f16(v.x, h0, l0); split_f16(v.y, h1, l1);
        split_f16(v.z, h2, l2); split_f16(v.w, h3, l3);
        dst[(2 * i) * NCHUNK]     = make_uint2((uint32_t)h0 | ((uint32_t)h1 << 16),
                                               (uint32_t)l0 | ((uint32_t)l1 << 16));
        dst[(2 * i + 1) * NCHUNK] = make_uint2((uint32_t)h2 | ((uint32_t)h3 << 16),
                                               (uint32_t)l2 | ((uint32_t)l3 << 16));
    }
    g_halfnorm[kc] = 0.5f * s;
}

// ---------------- main kernel ----------------
__device__ __forceinline__ void prefetch_chunk(uint32_t sbm, int buf, int ch, int tid) {
    // 32 rows x 128 uint2 = 32 KB = 2048 x 16B
    const char* src = (const char*)g_bsplit + (size_t)ch * 32768;
#pragma unroll
    for (int i = 0; i < 8; i++) {
        int idx = tid + i * TPB;           // 0..2047
        int r = idx >> 6, u = idx & 63;
        uint32_t dst = sbm + (buf ? OFF_B1 : OFF_B0) + r * (SBROW * 8) + u * 16;
        CP_ASYNC16(dst, src + r * 1024 + u * 16);
    }
}

template <int OutMode>
__global__ __launch_bounds__(TPB, 2) void vq_mma_kernel(
    const float* __restrict__ action, const float* __restrict__ centroids,
    void* __restrict__ out, int N) {
    extern __shared__ char smem[];
    const uint32_t sbm = smem_u32(smem);
    const int tid = threadIdx.x;
    const int w = tid >> 5;
    const int lane = tid & 31;
    const int g = lane >> 2;     // group id 0..7
    const int t = lane & 3;      // thread-in-group 0..3

    const int ntiles = (blockIdx.x + GRID_P < NTILES_TOT) ? 2 : 1;
    const int total_chunks = ntiles * NCHUNKS;

    // prime B pipeline (chunk stream repeats every NCHUNKS, shared by all tiles)
    prefetch_chunk(sbm, 0, 0, tid);
    CP_COMMIT();
    prefetch_chunk(sbm, 1, 1, tid);
    CP_COMMIT();

    // stage halfnorms once
    {
        const float4* src = (const float4*)g_halfnorm;
#pragma unroll
        for (int i = 0; i < 2; i++) {
            int idx = tid + i * TPB;
            *(float4*)(smem + OFF_HN + idx * 16) = src[idx];
        }
    }

    int cc = 0;   // running chunk counter across tiles

    for (int ti = 0; ti < ntiles; ti++) {
        const int tile = blockIdx.x + ti * GRID_P;

        // stage A tile [128][64] fp32 -> padded smem
        {
            const float4* src = (const float4*)(action + (size_t)tile * MTILE * D);
#pragma unroll
            for (int i = 0; i < 8; i++) {
                int idx = tid + i * TPB;
                int r = idx >> 4, c4 = idx & 15;
                *(float4*)(smem + OFF_A + r * (SA * 4) + c4 * 16) = src[idx];
            }
        }
        __syncthreads();

        // A fragments (fp16 h/l split), reused across all chunks of this tile.
        const int r0 = w * 16 + g;
        const int r1 = r0 + 8;
        uint32_t ah[4][4], al[4][4];
#pragma unroll
        for (int ks = 0; ks < 4; ks++) {
            const int cb = ks * 16 + 2 * t;
#pragma unroll
            for (int half = 0; half < 2; half++) {      // k-subgroup: +0 / +8
                float2 x0 = *(const float2*)(smem + OFF_A + (r0 * SA + cb + 8 * half) * 4);
                float2 x1 = *(const float2*)(smem + OFF_A + (r1 * SA + cb + 8 * half) * 4);
                uint16_t h0a, l0a, h0b, l0b, h1a, l1a, h1b, l1b;
                split_f16(x0.x, h0a, l0a); split_f16(x0.y, h0b, l0b);
                split_f16(x1.x, h1a, l1a); split_f16(x1.y, h1b, l1b);
                ah[ks][0 + 2 * half] = (uint32_t)h0a | ((uint32_t)h0b << 16);
                al[ks][0 + 2 * half] = (uint32_t)l0a | ((uint32_t)l0b << 16);
                ah[ks][1 + 2 * half] = (uint32_t)h1a | ((uint32_t)h1b << 16);
                al[ks][1 + 2 * half] = (uint32_t)l1a | ((uint32_t)l1b << 16);
            }
        }

        float best0 = -3.402823466e38f, best1 = -3.402823466e38f;
        int bk0 = 0, bk1 = 0;

        const uint32_t browoff = (uint32_t)(t * SBROW + g) * 8;   // (kpair=t, n=g)

        for (int ch = 0; ch < NCHUNKS; ch++, cc++) {
            CP_WAIT1();
            __syncthreads();
            const char* bbase = (const char*)smem + ((cc & 1) ? OFF_B1 : OFF_B0) + browoff;
            const float* hn = (const float*)(smem + OFF_HN) + ch * NCHUNK;

#pragma unroll
            for (int ng = 0; ng < 4; ng++) {
                float accH[4][4], accL[4][4];
#pragma unroll
                for (int q = 0; q < 4; q++)
#pragma unroll
                    for (int j = 0; j < 4; j++) { accH[q][j] = 0.f; accL[q][j] = 0.f; }

#pragma unroll
                for (int ks = 0; ks < 4; ks++) {
                    uint2 u0[4], u1[4];
#pragma unroll
                    for (int q = 0; q < 4; q++) {
                        const char* p0 = bbase + (uint32_t)ks * (8 * SBROW * 8) +
                                         (uint32_t)(ng * 32 + q * 8) * 8;
                        u0[q] = *(const uint2*)p0;                      // kpair 8ks+t
                        u1[q] = *(const uint2*)(p0 + 4 * SBROW * 8);    // kpair 8ks+t+4
                    }
#pragma unroll
                    for (int q = 0; q < 4; q++) {
                        mma_f16(accH[q][0], accH[q][1], accH[q][2], accH[q][3],
                                ah[ks][0], ah[ks][1], ah[ks][2], ah[ks][3], u0[q].x, u1[q].x);
                        mma_f16(accL[q][0], accL[q][1], accL[q][2], accL[q][3],
                                ah[ks][0], ah[ks][1], ah[ks][2], ah[ks][3], u0[q].y, u1[q].y);
                        mma_f16(accL[q][0], accL[q][1], accL[q][2], accL[q][3],
                                al[ks][0], al[ks][1], al[ks][2], al[ks][3], u0[q].x, u1[q].x);
                    }
                }

#pragma unroll
                for (int q = 0; q < 4; q++) {
                    const int n0 = ng * 32 + q * 8;
                    const int na = n0 + 2 * t, nb = na + 1;
                    float hna = hn[na], hnb = hn[nb];
                    float s0 = (accH[q][0] + accL[q][0]) - hna;   // row r0, col na
                    float s1 = (accH[q][1] + accL[q][1]) - hnb;   // row r0, col nb
                    float s2 = (accH[q][2] + accL[q][2]) - hna;   // row r1, col na
                    float s3 = (accH[q][3] + accL[q][3]) - hnb;   // row r1, col nb
                    const int base = ch * NCHUNK;
                    if (s0 > best0) { best0 = s0; bk0 = base + na; }
                    if (s1 > best0) { best0 = s1; bk0 = base + nb; }
                    if (s2 > best1) { best1 = s2; bk1 = base + na; }
                    if (s3 > best1) { best1 = s3; bk1 = base + nb; }
                }
            }

            __syncthreads();
            {   // keep commit-group count aligned: always commit exactly one group
                const int nxt = cc + 2;
                if (nxt < total_chunks) prefetch_chunk(sbm, nxt & 1, nxt & (NCHUNKS - 1), tid);
                CP_COMMIT();
            }
        }

        // quad reduction, earliest index on ties
#pragma unroll
        for (int off = 1; off < 4; off <<= 1) {
            float ob = __shfl_xor_sync(0xffffffffu, best0, off);
            int ok = __shfl_xor_sync(0xffffffffu, bk0, off);
            if (ob > best0 || (ob == best0 && ok < bk0)) { best0 = ob; bk0 = ok; }
            ob = __shfl_xor_sync(0xffffffffu, best1, off);
            ok = __shfl_xor_sync(0xffffffffu, bk1, off);
            if (ob > best1 || (ob == best1 && ok < bk1)) { best1 = ob; bk1 = ok; }
        }
        if (t == 0) {
            ((int*)(smem + OFF_BK))[r0] = bk0;
            ((int*)(smem + OFF_BK))[r1] = bk1;
        }
        __syncthreads();

        // epilogue for this tile
        const int* sbk = (const int*)(smem + OFF_BK);
        const int pbase = tile * MTILE;
        if (OutMode == 1) {
            if (tid < MTILE) ((long long*)out)[pbase + tid] = (long long)sbk[tid];
            float* rbase = (float*)out + 2 * (size_t)N;
#pragma unroll
            for (int i = 0; i < 8; i++) {
                int idx = tid + i * TPB;
                int row = idx >> 4, c4 = idx & 15;
                float4 a = *(const float4*)(smem + OFF_A + row * (SA * 4) + c4 * 16);
                float4 c = ((const float4*)(centroids + (size_t)sbk[row] * D))[c4];
                ((float4*)(rbase + (size_t)(pbase + row) * D))[c4] =
                    make_float4(a.x - c.x, a.y - c.y, a.z - c.z, a.w - c.w);
            }
        } else {
            float* o = (float*)out;
            if (tid < MTILE) o[pbase + tid] = (float)sbk[tid];   // exact for K<=2048
            float* rbase = o + (size_t)N;
#pragma unroll
            for (int i = 0; i < 8; i++) {
                int idx = tid + i * TPB;
                int row = idx >> 4, c4 = idx & 15;
                float4 a = *(const float4*)(smem + OFF_A + row * (SA * 4) + c4 * 16);
                float4 c = ((const float4*)(centroids + (size_t)sbk[row] * D))[c4];
                ((float4*)(rbase + (size_t)(pbase + row) * D))[c4] =
                    make_float4(a.x - c.x, a.y - c.y, a.z - c.z, a.w - c.w);
            }
        }
        __syncthreads();   // protect A smem before next tile's store
    }
}

// ---------------- launch ----------------
extern "C" void kernel_launch(void* const* d_in, const int* in_sizes, int n_in,
                              void* d_out, int out_size) {
    const float* action = (const float*)d_in[0];
    const float* centroids = (const float*)d_in[1];
    const int N = in_sizes[0] / D;   // 65536

    cudaFuncSetAttribute(vq_mma_kernel<0>, cudaFuncAttributeMaxDynamicSharedMemorySize, SMEM_TOTAL);
    cudaFuncSetAttribute(vq_mma_kernel<1>, cudaFuncAttributeMaxDynamicSharedMemorySize, SMEM_TOTAL);

    prep_kernel<<<(KTOT + 127) / 128, 128>>>(centroids);

    const long long os = (long long)out_size;
    if (os == (long long)N * (D + 2) || os == (long long)N * (D / 2 + 1)) {
        vq_mma_kernel<1><<<GRID_P, TPB, SMEM_TOTAL>>>(action, centroids, d_out, N);
    } else {
        vq_mma_kernel<0><<<GRID_P, TPB, SMEM_TOTAL>>>(action, centroids, d_out, N);
    }
}

// round 9
// speedup vs baseline: 1.0383x; 1.0383x over previous
#include <cuda_runtime.h>
#include <cuda_fp16.h>
#include <cstdint>

#define D 64
#define KTOT 2048
#define MTILE 128
#define NCHUNK 128
#define NCHUNKS (KTOT / NCHUNK)   // 16
#define TPB 128                   // 4 warps, each owns an m32 slab

#define SA 68             // A smem row stride (f32)
#define SBROW 132         // B smem row stride in uint2 (1056 B)

#define OFF_A  0
#define A_BYTES (MTILE * SA * 4)                  // 34816
#define OFF_B0 A_BYTES
#define B_BYTES (32 * SBROW * 8)                  // 33792 (32 k-pair rows)
#define OFF_B1 (OFF_B0 + B_BYTES)                 // 68608
#define OFF_HN (OFF_B1 + B_BYTES)                 // 102400
#define OFF_BK (OFF_HN + KTOT * 4)                // 110592
#define SMEM_TOTAL (OFF_BK + MTILE * 4)           // 111104

// ---------------- device scratch (no runtime allocation) ----------------
__device__ float g_halfnorm[KTOT];
// [chunk][kpair(32)][n(128)] -> (h0|h1<<16, l0|l1<<16)
__device__ __align__(16) uint2 g_bsplit[NCHUNKS * 32 * NCHUNK];

// ---------------- helpers ----------------
__device__ __forceinline__ uint32_t smem_u32(const void* p) {
    uint32_t a;
    asm("{ .reg .u64 t; cvta.to.shared.u64 t, %1; cvt.u32.u64 %0, t; }" : "=r"(a) : "l"(p));
    return a;
}
__device__ __forceinline__ void split_f16(float x, uint16_t& h, uint16_t& l) {
    __half hh = __float2half_rn(x);
    __half ll = __float2half_rn(x - __half2float(hh));
    h = __half_as_ushort(hh);
    l = __half_as_ushort(ll);
}
__device__ __forceinline__ void mma_f16(float& c0, float& c1, float& c2, float& c3,
                                        uint32_t a0, uint32_t a1, uint32_t a2, uint32_t a3,
                                        uint32_t b0, uint32_t b1) {
    asm volatile(
        "mma.sync.aligned.m16n8k16.row.col.f32.f16.f16.f32 "
        "{%0,%1,%2,%3}, {%4,%5,%6,%7}, {%8,%9}, {%0,%1,%2,%3};"
        : "+f"(c0), "+f"(c1), "+f"(c2), "+f"(c3)
        : "r"(a0), "r"(a1), "r"(a2), "r"(a3), "r"(b0), "r"(b1));
}
#define CP_ASYNC16(dst, src) \
    asm volatile("cp.async.cg.shared.global [%0], [%1], 16;" :: "r"(dst), "l"(src) : "memory")
#define CP_COMMIT() asm volatile("cp.async.commit_group;" ::: "memory")
#define CP_WAIT1()  asm volatile("cp.async.wait_group 1;" ::: "memory")

// ---------------- fused prep kernel (halfnorm + fp16 h/l split) ----------------
__global__ void prep_kernel(const float* __restrict__ c) {
    int kc = blockIdx.x * blockDim.x + threadIdx.x;   // one centroid per thread
    if (kc >= KTOT) return;
    const int chunk = kc >> 7, n = kc & 127;
    uint2* dst = g_bsplit + chunk * (32 * NCHUNK) + n;
    float s = 0.f;
#pragma unroll
    for (int i = 0; i < D / 4; i++) {
        float4 v = ((const float4*)(c + (size_t)kc * D))[i];
        s += v.x * v.x + v.y * v.y + v.z * v.z + v.w * v.w;
        uint16_t h0, l0, h1, l1, h2, l2, h3, l3;
        split_f16(v.x, h0, l0); split_f16(v.y, h1, l1);
        split_f16(v.z, h2, l2); split_f16(v.w, h3, l3);
        dst[(2 * i) * NCHUNK]     = make_uint2((uint32_t)h0 | ((uint32_t)h1 << 16),
                                               (uint32_t)l0 | ((uint32_t)l1 << 16));
        dst[(2 * i + 1) * NCHUNK] = make_uint2((uint32_t)h2 | ((uint32_t)h3 << 16),
                                               (uint32_t)l2 | ((uint32_t)l3 << 16));
    }
    g_halfnorm[kc] = 0.5f * s;
}

// ---------------- main kernel ----------------
__device__ __forceinline__ void prefetch_chunk(uint32_t sbm, int buf, int ch, int tid) {
    // 32 rows x 128 uint2 = 32 KB = 2048 x 16B
    const char* src = (const char*)g_bsplit + (size_t)ch * 32768;
#pragma unroll
    for (int i = 0; i < 16; i++) {
        int idx = tid + i * TPB;           // 0..2047
        int r = idx >> 6, u = idx & 63;
        uint32_t dst = sbm + (buf ? OFF_B1 : OFF_B0) + r * (SBROW * 8) + u * 16;
        CP_ASYNC16(dst, src + r * 1024 + u * 16);
    }
}

template <int OutMode>
__global__ __launch_bounds__(TPB, 2) void vq_mma_kernel(
    const float* __restrict__ action, const float* __restrict__ centroids,
    void* __restrict__ out, int N) {
    extern __shared__ char smem[];
    const uint32_t sbm = smem_u32(smem);
    const int tid = threadIdx.x;
    const int w = tid >> 5;      // warp 0..3, owns rows [w*32, w*32+32)
    const int lane = tid & 31;
    const int g = lane >> 2;     // group id 0..7
    const int t = lane & 3;      // thread-in-group 0..3

    prefetch_chunk(sbm, 0, 0, tid);
    CP_COMMIT();
    prefetch_chunk(sbm, 1, 1, tid);
    CP_COMMIT();

    // stage A tile [128][64] fp32 -> padded smem
    {
        const float4* src = (const float4*)(action + (size_t)blockIdx.x * MTILE * D);
#pragma unroll
        for (int i = 0; i < 16; i++) {
            int idx = tid + i * TPB;
            int r = idx >> 4, c4 = idx & 15;
            *(float4*)(smem + OFF_A + r * (SA * 4) + c4 * 16) = src[idx];
        }
    }
    // stage halfnorms
    {
        const float4* src = (const float4*)g_halfnorm;
#pragma unroll
        for (int i = 0; i < 4; i++) {
            int idx = tid + i * TPB;
            *(float4*)(smem + OFF_HN + idx * 16) = src[idx];
        }
    }
    __syncthreads();

    // A fragments (fp16 h/l split) for both m16 slabs of this warp's m32.
    // slab s: rows r0 = w*32 + s*16 + g, r1 = r0 + 8
    uint32_t ah[4][8], al[4][8];
#pragma unroll
    for (int ks = 0; ks < 4; ks++) {
        const int cb = ks * 16 + 2 * t;
#pragma unroll
        for (int s = 0; s < 2; s++) {
            const int r0 = w * 32 + s * 16 + g;
            const int r1 = r0 + 8;
#pragma unroll
            for (int half = 0; half < 2; half++) {      // k-subgroup: +0 / +8
                float2 x0 = *(const float2*)(smem + OFF_A + (r0 * SA + cb + 8 * half) * 4);
                float2 x1 = *(const float2*)(smem + OFF_A + (r1 * SA + cb + 8 * half) * 4);
                uint16_t h0a, l0a, h0b, l0b, h1a, l1a, h1b, l1b;
                split_f16(x0.x, h0a, l0a); split_f16(x0.y, h0b, l0b);
                split_f16(x1.x, h1a, l1a); split_f16(x1.y, h1b, l1b);
                ah[ks][s * 4 + 0 + 2 * half] = (uint32_t)h0a | ((uint32_t)h0b << 16);
                al[ks][s * 4 + 0 + 2 * half] = (uint32_t)l0a | ((uint32_t)l0b << 16);
                ah[ks][s * 4 + 1 + 2 * half] = (uint32_t)h1a | ((uint32_t)h1b << 16);
                al[ks][s * 4 + 1 + 2 * half] = (uint32_t)l1a | ((uint32_t)l1b << 16);
            }
        }
    }

    // best per thread for rows w*32 + g + {0, 8, 16, 24}
    float best[4];
    int bk[4];
#pragma unroll
    for (int j = 0; j < 4; j++) { best[j] = -3.402823466e38f; bk[j] = 0; }

    const uint32_t browoff = (uint32_t)(t * SBROW + g) * 8;   // (kpair=t, n=g)

    for (int ch = 0; ch < NCHUNKS; ch++) {
        CP_WAIT1();
        __syncthreads();
        const char* bbase = (const char*)smem + ((ch & 1) ? OFF_B1 : OFF_B0) + browoff;
        const float* hn = (const float*)(smem + OFF_HN) + ch * NCHUNK;

#pragma unroll
        for (int ng = 0; ng < 4; ng++) {
            float accH[4][8], accL[4][8];
            float hnv[4][2];
#pragma unroll
            for (int q = 0; q < 4; q++) {
                const int na = ng * 32 + q * 8 + 2 * t;
                hnv[q][0] = hn[na];
                hnv[q][1] = hn[na + 1];
#pragma unroll
                for (int s = 0; s < 2; s++) {
                    accH[q][s * 4 + 0] = -hnv[q][0];   // (r0, na)
                    accH[q][s * 4 + 1] = -hnv[q][1];   // (r0, nb)
                    accH[q][s * 4 + 2] = -hnv[q][0];   // (r1, na)
                    accH[q][s * 4 + 3] = -hnv[q][1];   // (r1, nb)
                }
#pragma unroll
                for (int j = 0; j < 8; j++) accL[q][j] = 0.f;
            }

#pragma unroll
            for (int ks = 0; ks < 4; ks++) {
                uint2 u0[4], u1[4];
#pragma unroll
                for (int q = 0; q < 4; q++) {
                    const char* p0 = bbase + (uint32_t)ks * (8 * SBROW * 8) +
                                     (uint32_t)(ng * 32 + q * 8) * 8;
                    u0[q] = *(const uint2*)p0;                      // kpair 8ks+t
                    u1[q] = *(const uint2*)(p0 + 4 * SBROW * 8);    // kpair 8ks+t+4
                }
#pragma unroll
                for (int q = 0; q < 4; q++) {
#pragma unroll
                    for (int s = 0; s < 2; s++) {
                        mma_f16(accH[q][s*4+0], accH[q][s*4+1], accH[q][s*4+2], accH[q][s*4+3],
                                ah[ks][s*4+0], ah[ks][s*4+1], ah[ks][s*4+2], ah[ks][s*4+3],
                                u0[q].x, u1[q].x);
                        mma_f16(accL[q][s*4+0], accL[q][s*4+1], accL[q][s*4+2], accL[q][s*4+3],
                                ah[ks][s*4+0], ah[ks][s*4+1], ah[ks][s*4+2], ah[ks][s*4+3],
                                u0[q].y, u1[q].y);
                        mma_f16(accL[q][s*4+0], accL[q][s*4+1], accL[q][s*4+2], accL[q][s*4+3],
                                al[ks][s*4+0], al[ks][s*4+1], al[ks][s*4+2], al[ks][s*4+3],
                                u0[q].x, u1[q].x);
                    }
                }
            }

            // argmax update (ascending n => strict '>' keeps earliest index)
#pragma unroll
            for (int q = 0; q < 4; q++) {
                const int na = ng * 32 + q * 8 + 2 * t;
                const int base = ch * NCHUNK;
#pragma unroll
                for (int s = 0; s < 2; s++) {
                    float s0 = accH[q][s*4+0] + accL[q][s*4+0];   // (row g+s*16,   na)
                    float s1 = accH[q][s*4+1] + accL[q][s*4+1];   // (row g+s*16,   na+1)
                    float s2 = accH[q][s*4+2] + accL[q][s*4+2];   // (row g+s*16+8, na)
                    float s3 = accH[q][s*4+3] + accL[q][s*4+3];   // (row g+s*16+8, na+1)
                    if (s0 > best[s*2+0]) { best[s*2+0] = s0; bk[s*2+0] = base + na; }
                    if (s1 > best[s*2+0]) { best[s*2+0] = s1; bk[s*2+0] = base + na + 1; }
                    if (s2 > best[s*2+1]) { best[s*2+1] = s2; bk[s*2+1] = base + na; }
                    if (s3 > best[s*2+1]) { best[s*2+1] = s3; bk[s*2+1] = base + na + 1; }
                }
            }
        }

        __syncthreads();
        {
            const int nxt = ch + 2;
            if (nxt < NCHUNKS) prefetch_chunk(sbm, nxt & 1, nxt, tid);
            CP_COMMIT();
        }
    }

    // quad reduction (over t), earliest index on ties
#pragma unroll
    for (int off = 1; off < 4; off <<= 1) {
#pragma unroll
        for (int j = 0; j < 4; j++) {
            float ob = __shfl_xor_sync(0xffffffffu, best[j], off);
            int ok = __shfl_xor_sync(0xffffffffu, bk[j], off);
            if (ob > best[j] || (ob == best[j] && ok < bk[j])) { best[j] = ob; bk[j] = ok; }
        }
    }
    if (t == 0) {
        int* sb = (int*)(smem + OFF_BK);
        sb[w * 32 + g]      = bk[0];   // s=0 rows: g, g+8
        sb[w * 32 + g + 8]  = bk[1];
        sb[w * 32 + g + 16] = bk[2];   // s=1 rows: g+16, g+24
        sb[w * 32 + g + 24] = bk[3];
    }
    __syncthreads();

    // epilogue
    const int* sbk = (const int*)(smem + OFF_BK);
    const int pbase = blockIdx.x * MTILE;
    if (OutMode == 1) {
        if (tid < MTILE) ((long long*)out)[pbase + tid] = (long long)sbk[tid];
        float* rbase = (float*)out + 2 * (size_t)N;
#pragma unroll
        for (int i = 0; i < 16; i++) {
            int idx = tid + i * TPB;
            int row = idx >> 4, c4 = idx & 15;
            float4 a = *(const float4*)(smem + OFF_A + row * (SA * 4) + c4 * 16);
            float4 c = ((const float4*)(centroids + (size_t)sbk[row] * D))[c4];
            ((float4*)(rbase + (size_t)(pbase + row) * D))[c4] =
                make_float4(a.x - c.x, a.y - c.y, a.z - c.z, a.w - c.w);
        }
    } else {
        float* o = (float*)out;
        if (tid < MTILE) o[pbase + tid] = (float)sbk[tid];   // exact for K<=2048
        float* rbase = o + (size_t)N;
#pragma unroll
        for (int i = 0; i < 16; i++) {
            int idx = tid + i * TPB;
            int row = idx >> 4, c4 = idx & 15;
            float4 a = *(const float4*)(smem + OFF_A + row * (SA * 4) + c4 * 16);
            float4 c = ((const float4*)(centroids + (size_t)sbk[row] * D))[c4];
            ((float4*)(rbase + (size_t)(pbase + row) * D))[c4] =
                make_float4(a.x - c.x, a.y - c.y, a.z - c.z, a.w - c.w);
        }
    }
}

// ---------------- launch ----------------
extern "C" void kernel_launch(void* const* d_in, const int* in_sizes, int n_in,
                              void* d_out, int out_size) {
    const float* action = (const float*)d_in[0];
    const float* centroids = (const float*)d_in[1];
    const int N = in_sizes[0] / D;   // 65536

    cudaFuncSetAttribute(vq_mma_kernel<0>, cudaFuncAttributeMaxDynamicSharedMemorySize, SMEM_TOTAL);
    cudaFuncSetAttribute(vq_mma_kernel<1>, cudaFuncAttributeMaxDynamicSharedMemorySize, SMEM_TOTAL);

    prep_kernel<<<(KTOT + 127) / 128, 128>>>(centroids);

    const int grid = N / MTILE;  // 512
    const long long os = (long long)out_size;
    if (os == (long long)N * (D + 2) || os == (long long)N * (D / 2 + 1)) {
        vq_mma_kernel<1><<<grid, TPB, SMEM_TOTAL>>>(action, centroids, d_out, N);
    } else {
        vq_mma_kernel<0><<<grid, TPB, SMEM_TOTAL>>>(action, centroids, d_out, N);
    }
}

// round 13
// speedup vs baseline: 1.0754x; 1.0357x over previous
#include <cuda_runtime.h>
#include <cuda_fp16.h>
#include <cstdint>

#define D 64
#define KTOT 2048
#define MTILE 128
#define NCHUNK 128
#define NCHUNKS (KTOT / NCHUNK)   // 16
#define TPB 128                   // 4 warps, each owns an m32 slab

#define SAH 72            // A fp16 plane row stride (fp16 elems; 144 B = 9*16, ldmatrix-aligned)
#define SBROW 132         // B smem row stride in uint2 (1056 B)

#define OFF_AH 0
#define AH_BYTES (MTILE * SAH * 2)                // 18432
#define OFF_AL AH_BYTES                           // 18432
#define OFF_B0 (2 * AH_BYTES)                     // 36864
#define B_BYTES (32 * SBROW * 8)                  // 33792
#define OFF_B1 (OFF_B0 + B_BYTES)                 // 70656
#define OFF_HN (OFF_B1 + B_BYTES)                 // 104448
#define OFF_BK (OFF_HN + KTOT * 4)                // 112640
#define SMEM_TOTAL (OFF_BK + MTILE * 4)           // 113152

// ---------------- device scratch (no runtime allocation) ----------------
__device__ float g_halfnorm[KTOT];
// [chunk][kpair(32)][n(128)] -> (h0|h1<<16, l0|l1<<16)
__device__ __align__(16) uint2 g_bsplit[NCHUNKS * 32 * NCHUNK];

// ---------------- helpers ----------------
__device__ __forceinline__ uint32_t smem_u32(const void* p) {
    uint32_t a;
    asm("{ .reg .u64 t; cvta.to.shared.u64 t, %1; cvt.u32.u64 %0, t; }" : "=r"(a) : "l"(p));
    return a;
}
__device__ __forceinline__ void split_f16(float x, uint16_t& h, uint16_t& l) {
    __half hh = __float2half_rn(x);
    __half ll = __float2half_rn(x - __half2float(hh));
    h = __half_as_ushort(hh);
    l = __half_as_ushort(ll);
}
__device__ __forceinline__ void mma_f16(float& c0, float& c1, float& c2, float& c3,
                                        uint32_t a0, uint32_t a1, uint32_t a2, uint32_t a3,
                                        uint32_t b0, uint32_t b1) {
    asm volatile(
        "mma.sync.aligned.m16n8k16.row.col.f32.f16.f16.f32 "
        "{%0,%1,%2,%3}, {%4,%5,%6,%7}, {%8,%9}, {%0,%1,%2,%3};"
        : "+f"(c0), "+f"(c1), "+f"(c2), "+f"(c3)
        : "r"(a0), "r"(a1), "r"(a2), "r"(a3), "r"(b0), "r"(b1));
}
__device__ __forceinline__ void ldsm_x4(uint32_t& r0, uint32_t& r1, uint32_t& r2, uint32_t& r3,
                                        uint32_t addr) {
    asm volatile("ldmatrix.sync.aligned.m8n8.x4.shared.b16 {%0,%1,%2,%3}, [%4];"
                 : "=r"(r0), "=r"(r1), "=r"(r2), "=r"(r3) : "r"(addr));
}
#define CP_ASYNC16(dst, src) \
    asm volatile("cp.async.cg.shared.global [%0], [%1], 16;" :: "r"(dst), "l"(src) : "memory")
#define CP_COMMIT() asm volatile("cp.async.commit_group;" ::: "memory")
#define CP_WAIT1()  asm volatile("cp.async.wait_group 1;" ::: "memory")

// ---------------- fused prep kernel (halfnorm + fp16 h/l split) ----------------
__global__ void prep_kernel(const float* __restrict__ c) {
    int kc = blockIdx.x * blockDim.x + threadIdx.x;   // one centroid per thread
    if (kc >= KTOT) return;
    const int chunk = kc >> 7, n = kc & 127;
    uint2* dst = g_bsplit + chunk * (32 * NCHUNK) + n;
    float s = 0.f;
#pragma unroll
    for (int i = 0; i < D / 4; i++) {
        float4 v = ((const float4*)(c + (size_t)kc * D))[i];
        s += v.x * v.x + v.y * v.y + v.z * v.z + v.w * v.w;
        uint16_t h0, l0, h1, l1, h2, l2, h3, l3;
        split_f16(v.x, h0, l0); split_f16(v.y, h1, l1);
        split_f16(v.z, h2, l2); split_f16(v.w, h3, l3);
        dst[(2 * i) * NCHUNK]     = make_uint2((uint32_t)h0 | ((uint32_t)h1 << 16),
                                               (uint32_t)l0 | ((uint32_t)l1 << 16));
        dst[(2 * i + 1) * NCHUNK] = make_uint2((uint32_t)h2 | ((uint32_t)h3 << 16),
                                               (uint32_t)l2 | ((uint32_t)l3 << 16));
    }
    g_halfnorm[kc] = 0.5f * s;
}

// ---------------- main kernel ----------------
__device__ __forceinline__ void prefetch_chunk(uint32_t sbm, int buf, int ch, int tid) {
    // 32 rows x 128 uint2 = 32 KB = 2048 x 16B
    const char* src = (const char*)g_bsplit + (size_t)ch * 32768;
#pragma unroll
    for (int i = 0; i < 16; i++) {
        int idx = tid + i * TPB;           // 0..2047
        int r = idx >> 6, u = idx & 63;
        uint32_t dst = sbm + (buf ? OFF_B1 : OFF_B0) + r * (SBROW * 8) + u * 16;
        CP_ASYNC16(dst, src + r * 1024 + u * 16);
    }
}

template <int OutMode>
__global__ __launch_bounds__(TPB, 2) void vq_mma_kernel(
    const float* __restrict__ action, const float* __restrict__ centroids,
    void* __restrict__ out, int N) {
    extern __shared__ char smem[];
    const uint32_t sbm = smem_u32(smem);
    const int tid = threadIdx.x;
    const int w = tid >> 5;      // warp 0..3, owns rows [w*32, w*32+32)
    const int lane = tid & 31;
    const int g = lane >> 2;     // group id 0..7
    const int t = lane & 3;      // thread-in-group 0..3

    prefetch_chunk(sbm, 0, 0, tid);
    CP_COMMIT();
    prefetch_chunk(sbm, 1, 1, tid);
    CP_COMMIT();

    // stage A tile [128][64]: split fp32 -> fp16 h/l planes (stride SAH fp16)
    {
        const float4* src = (const float4*)(action + (size_t)blockIdx.x * MTILE * D);
#pragma unroll
        for (int i = 0; i < 16; i++) {
            int idx = tid + i * TPB;           // 2048 float4
            int r = idx >> 4, c4 = idx & 15;   // row, group of 4 cols
            float4 v = src[idx];
            uint16_t h0, l0, h1, l1, h2, l2, h3, l3;
            split_f16(v.x, h0, l0); split_f16(v.y, h1, l1);
            split_f16(v.z, h2, l2); split_f16(v.w, h3, l3);
            uint32_t off = (uint32_t)r * (SAH * 2) + (uint32_t)c4 * 8;
            *(uint2*)(smem + OFF_AH + off) =
                make_uint2((uint32_t)h0 | ((uint32_t)h1 << 16),
                           (uint32_t)h2 | ((uint32_t)h3 << 16));
            *(uint2*)(smem + OFF_AL + off) =
                make_uint2((uint32_t)l0 | ((uint32_t)l1 << 16),
                           (uint32_t)l2 | ((uint32_t)l3 << 16));
        }
    }
    // stage halfnorms
    {
        const float4* src = (const float4*)g_halfnorm;
#pragma unroll
        for (int i = 0; i < 4; i++) {
            int idx = tid + i * TPB;
            *(float4*)(smem + OFF_HN + idx * 16) = src[idx];
        }
    }
    __syncthreads();

    // ldmatrix base addresses (per s-slab, per plane); advance by 32B per ks.
    // lanes 0-15 -> rows of the two m8 row-blocks at col 0; lanes 16-31 -> col +8
    const int arow = w * 32 + (lane & 15);
    const uint32_t acol8 = ((lane >> 4) & 1) * 16;   // +8 fp16 = 16 B
    uint32_t aaddr[2][2];                            // [s][plane]
#pragma unroll
    for (int s = 0; s < 2; s++) {
        uint32_t rowoff = (uint32_t)(arow + s * 16) * (SAH * 2) + acol8;
        aaddr[s][0] = sbm + OFF_AH + rowoff;
        aaddr[s][1] = sbm + OFF_AL + rowoff;
    }

    // best per thread for rows w*32 + g + {0, 8, 16, 24}
    float best[4];
    int bk[4];
#pragma unroll
    for (int j = 0; j < 4; j++) { best[j] = -3.402823466e38f; bk[j] = 0; }

    const uint32_t browoff = (uint32_t)(t * SBROW + g) * 8;   // (kpair=t, n=g)

    for (int ch = 0; ch < NCHUNKS; ch++) {
        CP_WAIT1();
        __syncthreads();
        const char* bbase = (const char*)smem + ((ch & 1) ? OFF_B1 : OFF_B0) + browoff;
        const float* hn = (const float*)(smem + OFF_HN) + ch * NCHUNK;

#pragma unroll
        for (int ng = 0; ng < 4; ng++) {
            float accH[4][8], accL[4][8];
#pragma unroll
            for (int q = 0; q < 4; q++) {
                const int na = ng * 32 + q * 8 + 2 * t;
                const float h0 = hn[na], h1 = hn[na + 1];
#pragma unroll
                for (int s = 0; s < 2; s++) {
                    accH[q][s * 4 + 0] = -h0;
                    accH[q][s * 4 + 1] = -h1;
                    accH[q][s * 4 + 2] = -h0;
                    accH[q][s * 4 + 3] = -h1;
                }
#pragma unroll
                for (int j = 0; j < 8; j++) accL[q][j] = 0.f;
            }

#pragma unroll
            for (int ks = 0; ks < 4; ks++) {
                // A fragments for this k-step via ldmatrix (h and l, both slabs)
                uint32_t ah[2][4], al[2][4];
#pragma unroll
                for (int s = 0; s < 2; s++) {
                    ldsm_x4(ah[s][0], ah[s][1], ah[s][2], ah[s][3], aaddr[s][0] + ks * 32);
                    ldsm_x4(al[s][0], al[s][1], al[s][2], al[s][3], aaddr[s][1] + ks * 32);
                }
                uint2 u0[4], u1[4];
#pragma unroll
                for (int q = 0; q < 4; q++) {
                    const char* p0 = bbase + (uint32_t)ks * (8 * SBROW * 8) +
                                     (uint32_t)(ng * 32 + q * 8) * 8;
                    u0[q] = *(const uint2*)p0;                      // kpair 8ks+t
                    u1[q] = *(const uint2*)(p0 + 4 * SBROW * 8);    // kpair 8ks+t+4
                }
#pragma unroll
                for (int q = 0; q < 4; q++) {
#pragma unroll
                    for (int s = 0; s < 2; s++) {
                        mma_f16(accH[q][s*4+0], accH[q][s*4+1], accH[q][s*4+2], accH[q][s*4+3],
                                ah[s][0], ah[s][1], ah[s][2], ah[s][3], u0[q].x, u1[q].x);
                        mma_f16(accL[q][s*4+0], accL[q][s*4+1], accL[q][s*4+2], accL[q][s*4+3],
                                ah[s][0], ah[s][1], ah[s][2], ah[s][3], u0[q].y, u1[q].y);
                        mma_f16(accL[q][s*4+0], accL[q][s*4+1], accL[q][s*4+2], accL[q][s*4+3],
                                al[s][0], al[s][1], al[s][2], al[s][3], u0[q].x, u1[q].x);
                    }
                }
            }

            // argmax update (ascending n => strict '>' keeps earliest index)
#pragma unroll
            for (int q = 0; q < 4; q++) {
                const int na = ng * 32 + q * 8 + 2 * t;
                const int base = ch * NCHUNK;
#pragma unroll
                for (int s = 0; s < 2; s++) {
                    float s0 = accH[q][s*4+0] + accL[q][s*4+0];   // (row g+s*16,   na)
                    float s1 = accH[q][s*4+1] + accL[q][s*4+1];   // (row g+s*16,   na+1)
                    float s2 = accH[q][s*4+2] + accL[q][s*4+2];   // (row g+s*16+8, na)
                    float s3 = accH[q][s*4+3] + accL[q][s*4+3];   // (row g+s*16+8, na+1)
                    if (s0 > best[s*2+0]) { best[s*2+0] = s0; bk[s*2+0] = base + na; }
                    if (s1 > best[s*2+0]) { best[s*2+0] = s1; bk[s*2+0] = base + na + 1; }
                    if (s2 > best[s*2+1]) { best[s*2+1] = s2; bk[s*2+1] = base + na; }
                    if (s3 > best[s*2+1]) { best[s*2+1] = s3; bk[s*2+1] = base + na + 1; }
                }
            }
        }

        __syncthreads();
        {
            const int nxt = ch + 2;
            if (nxt < NCHUNKS) prefetch_chunk(sbm, nxt & 1, nxt, tid);
            CP_COMMIT();
        }
    }

    // quad reduction (over t), earliest index on ties
#pragma unroll
    for (int off = 1; off < 4; off <<= 1) {
#pragma unroll
        for (int j = 0; j < 4; j++) {
            float ob = __shfl_xor_sync(0xffffffffu, best[j], off);
            int ok = __shfl_xor_sync(0xffffffffu, bk[j], off);
            if (ob > best[j] || (ob == best[j] && ok < bk[j])) { best[j] = ob; bk[j] = ok; }
        }
    }
    if (t == 0) {
        int* sb = (int*)(smem + OFF_BK);
        sb[w * 32 + g]      = bk[0];
        sb[w * 32 + g + 8]  = bk[1];
        sb[w * 32 + g + 16] = bk[2];
        sb[w * 32 + g + 24] = bk[3];
    }
    __syncthreads();

    // epilogue (reload A from gmem; residual = a - c_best)
    const int* sbk = (const int*)(smem + OFF_BK);
    const int pbase = blockIdx.x * MTILE;
    const float4* asrc = (const float4*)(action + (size_t)pbase * D);
    if (OutMode == 1) {
        if (tid < MTILE) ((long long*)out)[pbase + tid] = (long long)sbk[tid];
        float* rbase = (float*)out + 2 * (size_t)N;
#pragma unroll
        for (int i = 0; i < 16; i++) {
            int idx = tid + i * TPB;
            int row = idx >> 4, c4 = idx & 15;
            float4 a = asrc[idx];
            float4 c = ((const float4*)(centroids + (size_t)sbk[row] * D))[c4];
            ((float4*)(rbase + (size_t)(pbase + row) * D))[c4] =
                make_float4(a.x - c.x, a.y - c.y, a.z - c.z, a.w - c.w);
        }
    } else {
        float* o = (float*)out;
        if (tid < MTILE) o[pbase + tid] = (float)sbk[tid];   // exact for K<=2048
        float* rbase = o + (size_t)N;
#pragma unroll
        for (int i = 0; i < 16; i++) {
            int idx = tid + i * TPB;
            int row = idx >> 4, c4 = idx & 15;
            float4 a = asrc[idx];
            float4 c = ((const float4*)(centroids + (size_t)sbk[row] * D))[c4];
            ((float4*)(rbase + (size_t)(pbase + row) * D))[c4] =
                make_float4(a.x - c.x, a.y - c.y, a.z - c.z, a.w - c.w);
        }
    }
}

// ---------------- launch ----------------
extern "C" void kernel_launch(void* const* d_in, const int* in_sizes, int n_in,
                              void* d_out, int out_size) {
    const float* action = (const float*)d_in[0];
    const float* centroids = (const float*)d_in[1];
    const int N = in_sizes[0] / D;   // 65536

    cudaFuncSetAttribute(vq_mma_kernel<0>, cudaFuncAttributeMaxDynamicSharedMemorySize, SMEM_TOTAL);
    cudaFuncSetAttribute(vq_mma_kernel<1>, cudaFuncAttributeMaxDynamicSharedMemorySize, SMEM_TOTAL);

    prep_kernel<<<(KTOT + 127) / 128, 128>>>(centroids);

    const int grid = N / MTILE;  // 512
    const long long os = (long long)out_size;
    if (os == (long long)N * (D + 2) || os == (long long)N * (D / 2 + 1)) {
        vq_mma_kernel<1><<<grid, TPB, SMEM_TOTAL>>>(action, centroids, d_out, N);
    } else {
        vq_mma_kernel<0><<<grid, TPB, SMEM_TOTAL>>>(action, centroids, d_out, N);
    }
}